// round 9
// baseline (speedup 1.0000x reference)
#include <cuda_runtime.h>
#include <cuda_bf16.h>

#define N_BATCH 4096
#define T_SEQ   200
#define PADK    10

typedef unsigned long long u64;

// ---------------- device scratch: PRE-DUPLICATED transposed weights ----------------
// Each entry is a u64 = {w, w} (same fp32 in both halves) ready for fma.rn.f32x2.
// wd1[(k*128 + jg)*4 + jj] = dup(W1[(jg + 128*jj)*128 + k])   k<128, jg<128, jj<4
__device__ __align__(16) u64 g_wd1[128 * 128 * 4];   // 512 KB
// wd2[(k*128 + jg)*2 + jj] = dup(W2[(jg + 128*jj)*512 + k])   k<512, jg<128, jj<2
__device__ __align__(16) u64 g_wd2[512 * 128 * 2];   // 1 MB
// wd3[k*128 + jg]          = dup(W3[jg*256 + k])              k<256, jg<128
__device__ __align__(16) u64 g_wd3[256 * 128];       // 256 KB

// ---------------- f32x2 helpers ----------------
__device__ __forceinline__ u64 pk2(float lo, float hi) {
    u64 r; asm("mov.b64 %0, {%1,%2};" : "=l"(r) : "f"(lo), "f"(hi)); return r;
}
__device__ __forceinline__ float2 upk(u64 v) {
    float2 f; asm("mov.b64 {%0,%1}, %2;" : "=f"(f.x), "=f"(f.y) : "l"(v)); return f;
}
__device__ __forceinline__ void fma2(u64& d, u64 a, u64 b) {
    asm("fma.rn.f32x2 %0, %1, %2, %0;" : "+l"(d) : "l"(a), "l"(b));
}
__device__ __forceinline__ u64 dup1(float w) { return pk2(w, w); }

// ---------------- 1) weight transpose + duplicate (coalesced reads) ----------------
__global__ void transpose_kernel(const float* __restrict__ W1,
                                 const float* __restrict__ W2,
                                 const float* __restrict__ W3) {
    int idx = blockIdx.x * blockDim.x + threadIdx.x;
    if (idx < 65536) {                         // W1: 512x128 (j*128+k)
        int j = idx >> 7, k = idx & 127;
        int jg = j & 127, jj = j >> 7;
        g_wd1[(k * 128 + jg) * 4 + jj] = dup1(W1[idx]);
    } else if (idx < 65536 + 131072) {         // W2: 256x512 (j*512+k)
        int i2 = idx - 65536;
        int j = i2 >> 9, k = i2 & 511;
        int jg = j & 127, jj = j >> 7;
        g_wd2[(k * 128 + jg) * 2 + jj] = dup1(W2[i2]);
    } else if (idx < 65536 + 131072 + 32768) { // W3: 128x256 (j*256+k)
        int i3 = idx - 65536 - 131072;
        int j = i3 >> 8, k = i3 & 255;
        g_wd3[k * 128 + j] = dup1(W3[i3]);
    }
}

// ---------------- 2) fused pool + MLP: 16 rows per block, 512 threads ----------------
// Activation u64 word = (row 2p value, row 2p+1 value), layout [k][pair], PADK=10.
// Smem:
//   A1  = S        : 512*10 u64 (40KB)  layer1 out; reused as A3 (layer3 out)
//   B2  = S+5120   : 256*10 u64 (20KB)  layer2 out; overlays BIN (pooled in)
__global__ void __launch_bounds__(512, 2) mlp_kernel(
        const int*   __restrict__ x,
        const int*   __restrict__ lengths,
        const float* __restrict__ emb,
        const float* __restrict__ b1,
        const float* __restrict__ b2,
        const float* __restrict__ b3,
        const float* __restrict__ W4,
        const float* __restrict__ b4,
        float* __restrict__ out) {
    __shared__ __align__(16) u64 S[512 * PADK + 256 * PADK];   // 60 KB
    u64* A1  = S;                      // [k*PADK + p], k<512
    u64* B2  = S + 512 * PADK;         // [k*PADK + p], k<256
    u64* BIN = B2;                     // [k*PADK + p], k<128 (dead after layer 1)
    u64* A3  = A1;                     // [j*PADK + p], j<128 (layer 3 out)

    int tid   = threadIdx.x;
    int w     = tid >> 5;              // warp 0..15 == row within block
    int lane  = tid & 31;
    int jg    = tid & 127;             // output-group index
    int pbase = (tid >> 7) * 2;        // pair base: 0,2,4,6 (uniform per warp)
    int r0    = blockIdx.x * 16;

    // ---- pooling: warp w pools row r0+w ----
    {
        int row = r0 + w;
        const int* xr = x + row * T_SEQ;
        int len = lengths[row];
        const float4* emb4 = (const float4*)emb;
        float4 acc = make_float4(0.f, 0.f, 0.f, 0.f);
        int t = 0;
        for (; t + 8 <= len; t += 8) {
            int4 ia = *(const int4*)(xr + t);
            int4 ib = *(const int4*)(xr + t + 4);
            float4 v0 = emb4[ia.x * 32 + lane];
            float4 v1 = emb4[ia.y * 32 + lane];
            float4 v2 = emb4[ia.z * 32 + lane];
            float4 v3 = emb4[ia.w * 32 + lane];
            float4 v4 = emb4[ib.x * 32 + lane];
            float4 v5 = emb4[ib.y * 32 + lane];
            float4 v6 = emb4[ib.z * 32 + lane];
            float4 v7 = emb4[ib.w * 32 + lane];
            acc.x += ((v0.x + v1.x) + (v2.x + v3.x)) + ((v4.x + v5.x) + (v6.x + v7.x));
            acc.y += ((v0.y + v1.y) + (v2.y + v3.y)) + ((v4.y + v5.y) + (v6.y + v7.y));
            acc.z += ((v0.z + v1.z) + (v2.z + v3.z)) + ((v4.z + v5.z) + (v6.z + v7.z));
            acc.w += ((v0.w + v1.w) + (v2.w + v3.w)) + ((v4.w + v5.w) + (v6.w + v7.w));
        }
        for (; t < len; ++t) {
            float4 a = emb4[xr[t] * 32 + lane];
            acc.x += a.x; acc.y += a.y; acc.z += a.z; acc.w += a.w;
        }
        float inv = 1.0f / (float)len;
        acc.x *= inv; acc.y *= inv; acc.z *= inv; acc.w *= inv;

        float* Bf = (float*)BIN;                 // pair p = w>>1, half s = w&1
        int p = w >> 1, s = w & 1;
        Bf[((4 * lane + 0) * PADK + p) * 2 + s] = acc.x;
        Bf[((4 * lane + 1) * PADK + p) * 2 + s] = acc.y;
        Bf[((4 * lane + 2) * PADK + p) * 2 + s] = acc.z;
        Bf[((4 * lane + 3) * PADK + p) * 2 + s] = acc.w;
    }
    __syncthreads();

    // ---- layer 1: 128 -> 512; j = jg + 128*jj (jj<4), pairs pbase,pbase+1 ----
    {
        u64 acc[4][2];
        #pragma unroll
        for (int jj = 0; jj < 4; ++jj) { acc[jj][0] = 0ULL; acc[jj][1] = 0ULL; }

        #pragma unroll 2
        for (int k = 0; k < 128; ++k) {
            const u64* wp = g_wd1 + (k * 128 + jg) * 4;
            ulonglong2 wa = *(const ulonglong2*)(wp);       // dup w for jj=0,1 (LDG.128)
            ulonglong2 wb = *(const ulonglong2*)(wp + 2);   // dup w for jj=2,3 (LDG.128)
            ulonglong2 ap = *(const ulonglong2*)(BIN + k * PADK + pbase);  // uniform LDS.128
            fma2(acc[0][0], ap.x, wa.x); fma2(acc[0][1], ap.y, wa.x);
            fma2(acc[1][0], ap.x, wa.y); fma2(acc[1][1], ap.y, wa.y);
            fma2(acc[2][0], ap.x, wb.x); fma2(acc[2][1], ap.y, wb.x);
            fma2(acc[3][0], ap.x, wb.y); fma2(acc[3][1], ap.y, wb.y);
        }
        __syncthreads();   // all BIN reads done; B2 region reusable
        #pragma unroll
        for (int jj = 0; jj < 4; ++jj) {
            int n1 = jg + 128 * jj;
            float bj = b1[n1];
            float2 v0 = upk(acc[jj][0]);
            float2 v1 = upk(acc[jj][1]);
            ulonglong2 st;
            st.x = pk2(fmaxf(v0.x + bj, 0.f), fmaxf(v0.y + bj, 0.f));
            st.y = pk2(fmaxf(v1.x + bj, 0.f), fmaxf(v1.y + bj, 0.f));
            *(ulonglong2*)(A1 + n1 * PADK + pbase) = st;    // STS.128, conflict-free
        }
    }
    __syncthreads();

    // ---- layer 2: 512 -> 256; j = jg + 128*jj (jj<2), pairs pbase,pbase+1 ----
    {
        u64 acc[2][2];
        acc[0][0] = acc[0][1] = acc[1][0] = acc[1][1] = 0ULL;

        #pragma unroll 4
        for (int k = 0; k < 512; ++k) {
            ulonglong2 wa = *(const ulonglong2*)(g_wd2 + (k * 128 + jg) * 2);  // LDG.128
            ulonglong2 ap = *(const ulonglong2*)(A1 + k * PADK + pbase);       // uniform LDS.128
            fma2(acc[0][0], ap.x, wa.x); fma2(acc[0][1], ap.y, wa.x);
            fma2(acc[1][0], ap.x, wa.y); fma2(acc[1][1], ap.y, wa.y);
        }
        #pragma unroll
        for (int jj = 0; jj < 2; ++jj) {
            int j = jg + 128 * jj;
            float bj = b2[j];
            float2 v0 = upk(acc[jj][0]);
            float2 v1 = upk(acc[jj][1]);
            ulonglong2 st;
            st.x = pk2(fmaxf(v0.x + bj, 0.f), fmaxf(v0.y + bj, 0.f));
            st.y = pk2(fmaxf(v1.x + bj, 0.f), fmaxf(v1.y + bj, 0.f));
            *(ulonglong2*)(B2 + j * PADK + pbase) = st;     // BIN dead; safe
        }
    }
    __syncthreads();

    // ---- layer 3: 256 -> 128; j = jg, pairs pbase,pbase+1 ----
    {
        u64 acc0 = 0ULL, acc1 = 0ULL;
        #pragma unroll 8
        for (int k = 0; k < 256; ++k) {
            u64 wd = g_wd3[k * 128 + jg];                   // LDG.64, coalesced, pre-dup'd
            ulonglong2 ap = *(const ulonglong2*)(B2 + k * PADK + pbase);   // uniform LDS.128
            fma2(acc0, ap.x, wd); fma2(acc1, ap.y, wd);
        }
        float bj = b3[jg];
        float2 v0 = upk(acc0);
        float2 v1 = upk(acc1);
        ulonglong2 st;
        st.x = pk2(fmaxf(v0.x + bj, 0.f), fmaxf(v0.y + bj, 0.f));
        st.y = pk2(fmaxf(v1.x + bj, 0.f), fmaxf(v1.y + bj, 0.f));
        *(ulonglong2*)(A3 + jg * PADK + pbase) = st;        // A1 reads finished 2 syncs ago
    }
    __syncthreads();

    // ---- layer 4: 128 -> 2 (one warp: r = tid>>1, jo = tid&1) ----
    if (tid < 32) {
        int r  = tid >> 1;             // 0..15
        int jo = tid & 1;
        int p = r >> 1, h = r & 1;
        float acc = b4[jo];
        #pragma unroll 8
        for (int k = 0; k < 128; ++k) {
            float2 v = upk(A3[k * PADK + p]);
            acc += (h ? v.y : v.x) * W4[jo * 128 + k];
        }
        out[(r0 + r) * 2 + jo] = acc;
    }
}

// ---------------- launch ----------------
extern "C" void kernel_launch(void* const* d_in, const int* in_sizes, int n_in,
                              void* d_out, int out_size) {
    const int*   x       = (const int*)  d_in[0];
    const int*   lengths = (const int*)  d_in[1];
    const float* emb     = (const float*)d_in[2];
    const float* W1      = (const float*)d_in[3];
    const float* b1      = (const float*)d_in[4];
    const float* W2      = (const float*)d_in[5];
    const float* b2      = (const float*)d_in[6];
    const float* W3      = (const float*)d_in[7];
    const float* b3      = (const float*)d_in[8];
    const float* W4      = (const float*)d_in[9];
    const float* b4      = (const float*)d_in[10];
    float* out = (float*)d_out;

    transpose_kernel<<<(229376 + 255) / 256, 256>>>(W1, W2, W3);
    mlp_kernel<<<N_BATCH / 16, 512>>>(x, lengths, emb, b1, b2, b3, W4, b4, out);
}

// round 11
// speedup vs baseline: 1.1448x; 1.1448x over previous
#include <cuda_runtime.h>
#include <cuda_bf16.h>

#define N_BATCH 4096
#define T_SEQ   200

typedef unsigned long long u64;

// ---------------- device scratch (no allocs allowed) ----------------
__device__ float g_pooled[N_BATCH * 128];                      // 2 MB  [row][k]
__device__ __align__(16) u64 g_h1[512 * 2048];                 // 8 MB  [j][rowpair]
__device__ __align__(16) u64 g_h2[256 * 2048];                 // 4 MB  [j][rowpair]
__device__ __align__(16) u64 g_h3[128 * 2048];                 // 2 MB  [j][rowpair]

// transposed weights; j decomposed as (js, jj, jgi):
// wt1[((k*2+js)*64 + jgi)*4 + jj] = W1[(js*256 + jj*64 + jgi)*128 + k]
__device__ float g_wt1[128 * 512];
// wt2[((k*2+js)*64 + jgi)*2 + jj] = W2[(js*128 + jj*64 + jgi)*512 + k]
__device__ float g_wt2[512 * 256];
// wt3[(k*64 + jgi)*2 + jj]        = W3[(jj*64 + jgi)*256 + k]
__device__ float g_wt3[256 * 128];

// ---------------- f32x2 helpers ----------------
__device__ __forceinline__ u64 pk2(float lo, float hi) {
    u64 r; asm("mov.b64 %0, {%1,%2};" : "=l"(r) : "f"(lo), "f"(hi)); return r;
}
__device__ __forceinline__ float2 upk(u64 v) {
    float2 f; asm("mov.b64 {%0,%1}, %2;" : "=f"(f.x), "=f"(f.y) : "l"(v)); return f;
}
__device__ __forceinline__ void fma2(u64& d, u64 a, u64 b) {
    asm("fma.rn.f32x2 %0, %1, %2, %0;" : "+l"(d) : "l"(a), "l"(b));
}

// ---------------- 0) prep: pooling (512 blocks) + weight transpose (896 blocks) ----------------
__global__ void prep_kernel(const int* __restrict__ x,
                            const int* __restrict__ lengths,
                            const float* __restrict__ emb,
                            const float* __restrict__ W1,
                            const float* __restrict__ W2,
                            const float* __restrict__ W3) {
    if (blockIdx.x < 512) {
        int gwarp = (blockIdx.x * 256 + threadIdx.x) >> 5;   // row
        int lane  = threadIdx.x & 31;
        const int* xr = x + gwarp * T_SEQ;
        int len = lengths[gwarp];
        const float4* emb4 = (const float4*)emb;
        float4 acc = make_float4(0.f, 0.f, 0.f, 0.f);
        int t = 0;
        for (; t + 8 <= len; t += 8) {
            int4 ia = *(const int4*)(xr + t);
            int4 ib = *(const int4*)(xr + t + 4);
            float4 v0 = emb4[ia.x * 32 + lane];
            float4 v1 = emb4[ia.y * 32 + lane];
            float4 v2 = emb4[ia.z * 32 + lane];
            float4 v3 = emb4[ia.w * 32 + lane];
            float4 v4 = emb4[ib.x * 32 + lane];
            float4 v5 = emb4[ib.y * 32 + lane];
            float4 v6 = emb4[ib.z * 32 + lane];
            float4 v7 = emb4[ib.w * 32 + lane];
            acc.x += ((v0.x + v1.x) + (v2.x + v3.x)) + ((v4.x + v5.x) + (v6.x + v7.x));
            acc.y += ((v0.y + v1.y) + (v2.y + v3.y)) + ((v4.y + v5.y) + (v6.y + v7.y));
            acc.z += ((v0.z + v1.z) + (v2.z + v3.z)) + ((v4.z + v5.z) + (v6.z + v7.z));
            acc.w += ((v0.w + v1.w) + (v2.w + v3.w)) + ((v4.w + v5.w) + (v6.w + v7.w));
        }
        for (; t < len; ++t) {
            float4 a = emb4[xr[t] * 32 + lane];
            acc.x += a.x; acc.y += a.y; acc.z += a.z; acc.w += a.w;
        }
        float inv = 1.0f / (float)len;
        acc.x *= inv; acc.y *= inv; acc.z *= inv; acc.w *= inv;
        ((float4*)g_pooled)[gwarp * 32 + lane] = acc;
    } else {
        int idx = (blockIdx.x - 512) * 256 + threadIdx.x;
        if (idx < 65536) {                          // W1: j<512, k<128
            int j = idx >> 7, k = idx & 127;
            int js = j >> 8, jj = (j >> 6) & 3, jgi = j & 63;
            g_wt1[((k * 2 + js) * 64 + jgi) * 4 + jj] = W1[idx];
        } else if (idx < 65536 + 131072) {          // W2: j<256, k<512
            int i2 = idx - 65536;
            int j = i2 >> 9, k = i2 & 511;
            int js = j >> 7, jj = (j >> 6) & 1, jgi = j & 63;
            g_wt2[((k * 2 + js) * 64 + jgi) * 2 + jj] = W2[i2];
        } else if (idx < 65536 + 131072 + 32768) {  // W3: j<128, k<256
            int i3 = idx - 65536 - 131072;
            int j = i3 >> 8, k = i3 & 255;
            int jj = j >> 6, jgi = j & 63;
            g_wt3[(k * 64 + jgi) * 2 + jj] = W3[i3];
        }
    }
}

// ---------------- 1) layer1: 128 -> 512 ----------------
// Block: 32 rows (16 rowpairs) x 256 j (js half). 512 thr: thread = 4j x 2rp.
__global__ void __launch_bounds__(512, 2) l1_kernel(const float* __restrict__ b1) {
    __shared__ __align__(16) u64 BIN[128 * 18];   // [k][rp], stride 18 (even)

    int tid   = threadIdx.x;
    int jgi   = tid & 63;
    int rpg_i = tid >> 6;                 // 0..7 (warp-uniform)
    int js    = blockIdx.x & 1;
    int rb    = blockIdx.x >> 1;          // 0..127
    int r0    = rb * 32;
    int rpg0  = rb * 16;

    // stage pooled rows -> pair-packed smem
    {
        int row = tid >> 4;               // 0..31
        int k0  = 4 * (tid & 15);
        int rp  = row >> 1, s = row & 1;
        float* Bf = (float*)BIN;
        #pragma unroll
        for (int h = 0; h < 2; ++h) {
            int kk = k0 + 64 * h;
            float4 v = *(const float4*)(g_pooled + (r0 + row) * 128 + kk);
            Bf[((kk + 0) * 18 + rp) * 2 + s] = v.x;
            Bf[((kk + 1) * 18 + rp) * 2 + s] = v.y;
            Bf[((kk + 2) * 18 + rp) * 2 + s] = v.z;
            Bf[((kk + 3) * 18 + rp) * 2 + s] = v.w;
        }
    }
    __syncthreads();

    u64 acc[4][2];
    #pragma unroll
    for (int jj = 0; jj < 4; ++jj) { acc[jj][0] = 0ULL; acc[jj][1] = 0ULL; }

    #pragma unroll 4
    for (int k = 0; k < 128; ++k) {
        float4 wv = *(const float4*)(g_wt1 + ((k * 2 + js) * 64 + jgi) * 4);  // LDG.128
        ulonglong2 ap = *(const ulonglong2*)(BIN + k * 18 + 2 * rpg_i);       // uniform LDS.128
        u64 w0 = pk2(wv.x, wv.x), w1 = pk2(wv.y, wv.y);
        u64 w2 = pk2(wv.z, wv.z), w3 = pk2(wv.w, wv.w);
        fma2(acc[0][0], ap.x, w0); fma2(acc[0][1], ap.y, w0);
        fma2(acc[1][0], ap.x, w1); fma2(acc[1][1], ap.y, w1);
        fma2(acc[2][0], ap.x, w2); fma2(acc[2][1], ap.y, w2);
        fma2(acc[3][0], ap.x, w3); fma2(acc[3][1], ap.y, w3);
    }

    #pragma unroll
    for (int jj = 0; jj < 4; ++jj) {
        int j = js * 256 + jj * 64 + jgi;
        float bj = b1[j];
        float2 v0 = upk(acc[jj][0]);
        float2 v1 = upk(acc[jj][1]);
        ulonglong2 st;
        st.x = pk2(fmaxf(v0.x + bj, 0.f), fmaxf(v0.y + bj, 0.f));
        st.y = pk2(fmaxf(v1.x + bj, 0.f), fmaxf(v1.y + bj, 0.f));
        *(ulonglong2*)(g_h1 + j * 2048 + rpg0 + 2 * rpg_i) = st;   // STG.128
    }
}

// ---------------- 2) layer2: 512 -> 256 ----------------
// Block: 32 rows x 128 j (js half). 512 thr: thread = 2j x 2rp. Two k-phases.
__global__ void __launch_bounds__(512, 2) l2_kernel(const float* __restrict__ b2) {
    __shared__ __align__(16) u64 A[256 * 18];     // [k-phase][rp], stride 18 (even)

    int tid   = threadIdx.x;
    int jgi   = tid & 63;
    int rpg_i = tid >> 6;                 // 0..7 (warp-uniform)
    int js    = blockIdx.x & 1;
    int rb    = blockIdx.x >> 1;          // 0..127
    int rpg0  = rb * 16;

    u64 acc[2][2];
    acc[0][0] = acc[0][1] = acc[1][0] = acc[1][1] = 0ULL;

    #pragma unroll
    for (int ph = 0; ph < 2; ++ph) {
        // stage h1[k in phase][16 rp]
        #pragma unroll
        for (int it = 0; it < 4; ++it) {
            int u2idx = tid + 512 * it;           // 0..2047
            int k = u2idx >> 3, rpp = u2idx & 7;
            ulonglong2 v = *(const ulonglong2*)(g_h1 + (ph * 256 + k) * 2048 + rpg0 + 2 * rpp);
            *(ulonglong2*)(A + k * 18 + 2 * rpp) = v;
        }
        __syncthreads();

        #pragma unroll 4
        for (int k = 0; k < 256; ++k) {
            int kg = ph * 256 + k;
            float2 wv = *(const float2*)(g_wt2 + ((kg * 2 + js) * 64 + jgi) * 2); // LDG.64
            ulonglong2 ap = *(const ulonglong2*)(A + k * 18 + 2 * rpg_i);         // uniform LDS.128
            u64 w0 = pk2(wv.x, wv.x), w1 = pk2(wv.y, wv.y);
            fma2(acc[0][0], ap.x, w0); fma2(acc[0][1], ap.y, w0);
            fma2(acc[1][0], ap.x, w1); fma2(acc[1][1], ap.y, w1);
        }
        __syncthreads();
    }

    #pragma unroll
    for (int jj = 0; jj < 2; ++jj) {
        int j = js * 128 + jj * 64 + jgi;
        float bj = b2[j];
        float2 v0 = upk(acc[0][0]), dummy0;  // placeholder to keep structure clear
        (void)dummy0;
        float2 va = upk(acc[jj][0]);
        float2 vb = upk(acc[jj][1]);
        ulonglong2 st;
        st.x = pk2(fmaxf(va.x + bj, 0.f), fmaxf(va.y + bj, 0.f));
        st.y = pk2(fmaxf(vb.x + bj, 0.f), fmaxf(vb.y + bj, 0.f));
        *(ulonglong2*)(g_h2 + j * 2048 + rpg0 + 2 * rpg_i) = st;   // STG.128
    }
}

// ---------------- 3) layer3: 256 -> 128 ----------------
// Block: 16 rows (8 rp) x 128 j. 512 thr: thread = 2j x 1rp.
__global__ void __launch_bounds__(512, 2) l3_kernel(const float* __restrict__ b3) {
    __shared__ __align__(16) u64 B3[256 * 10];    // [k][rp], stride 10 (EVEN: 16B-safe)

    int tid  = threadIdx.x;
    int jgi  = tid & 63;
    int rp_i = tid >> 6;                  // 0..7 (warp-uniform)
    int rb   = blockIdx.x;                // 0..255
    int rpg0 = rb * 8;

    // stage h2[256 k][8 rp]
    #pragma unroll
    for (int it = 0; it < 2; ++it) {
        int u2idx = tid + 512 * it;               // 0..1023
        int k = u2idx >> 2, rpp = u2idx & 3;
        ulonglong2 v = *(const ulonglong2*)(g_h2 + k * 2048 + rpg0 + 2 * rpp);
        *(ulonglong2*)(B3 + k * 10 + 2 * rpp) = v;     // even u64 index -> 16B aligned
    }
    __syncthreads();

    u64 acc0 = 0ULL, acc1 = 0ULL;
    #pragma unroll 8
    for (int k = 0; k < 256; ++k) {
        float2 wv = *(const float2*)(g_wt3 + (k * 64 + jgi) * 2);   // LDG.64
        u64 a = B3[k * 10 + rp_i];                                  // uniform LDS.64
        u64 w0 = pk2(wv.x, wv.x), w1 = pk2(wv.y, wv.y);
        fma2(acc0, a, w0);
        fma2(acc1, a, w1);
    }

    {
        int j0 = jgi, j1 = 64 + jgi;
        float bj0 = b3[j0], bj1 = b3[j1];
        float2 v0 = upk(acc0);
        float2 v1 = upk(acc1);
        g_h3[j0 * 2048 + rpg0 + rp_i] = pk2(fmaxf(v0.x + bj0, 0.f), fmaxf(v0.y + bj0, 0.f));
        g_h3[j1 * 2048 + rpg0 + rp_i] = pk2(fmaxf(v1.x + bj1, 0.f), fmaxf(v1.y + bj1, 0.f));
    }
}

// ---------------- 4) layer4: 128 -> 2 (one warp per rowpair) ----------------
__global__ void __launch_bounds__(256) l4_kernel(const float* __restrict__ W4,
                                                 const float* __restrict__ b4,
                                                 float* __restrict__ out) {
    int rpg  = blockIdx.x * 8 + (threadIdx.x >> 5);   // 0..2047
    int lane = threadIdx.x & 31;

    float a00 = 0.f, a01 = 0.f, a10 = 0.f, a11 = 0.f;
    #pragma unroll
    for (int c = 0; c < 4; ++c) {
        int k = lane + 32 * c;
        float2 h = upk(g_h3[k * 2048 + rpg]);
        float wa = W4[k], wb = W4[128 + k];
        a00 += h.x * wa; a01 += h.x * wb;
        a10 += h.y * wa; a11 += h.y * wb;
    }
    #pragma unroll
    for (int off = 16; off > 0; off >>= 1) {
        a00 += __shfl_xor_sync(0xffffffffu, a00, off);
        a01 += __shfl_xor_sync(0xffffffffu, a01, off);
        a10 += __shfl_xor_sync(0xffffffffu, a10, off);
        a11 += __shfl_xor_sync(0xffffffffu, a11, off);
    }
    if (lane == 0) {
        float4 st;
        st.x = a00 + b4[0];
        st.y = a01 + b4[1];
        st.z = a10 + b4[0];
        st.w = a11 + b4[1];
        *(float4*)(out + rpg * 4) = st;
    }
}

// ---------------- launch ----------------
extern "C" void kernel_launch(void* const* d_in, const int* in_sizes, int n_in,
                              void* d_out, int out_size) {
    const int*   x       = (const int*)  d_in[0];
    const int*   lengths = (const int*)  d_in[1];
    const float* emb     = (const float*)d_in[2];
    const float* W1      = (const float*)d_in[3];
    const float* b1      = (const float*)d_in[4];
    const float* W2      = (const float*)d_in[5];
    const float* b2      = (const float*)d_in[6];
    const float* W3      = (const float*)d_in[7];
    const float* b3      = (const float*)d_in[8];
    const float* W4      = (const float*)d_in[9];
    const float* b4      = (const float*)d_in[10];
    float* out = (float*)d_out;

    prep_kernel<<<1408, 256>>>(x, lengths, emb, W1, W2, W3);
    l1_kernel<<<256, 512>>>(b1);
    l2_kernel<<<256, 512>>>(b2);
    l3_kernel<<<256, 512>>>(b3);
    l4_kernel<<<256, 256>>>(W4, b4, out);
}

// round 13
// speedup vs baseline: 1.6782x; 1.4659x over previous
#include <cuda_runtime.h>
#include <cuda_bf16.h>

#define N_BATCH 4096
#define T_SEQ   200

typedef __nv_bfloat16  bf16;
typedef __nv_bfloat162 bf162;

// ================= device globals (split bf16) =================
__device__ __align__(16) bf16 g_phi[4096 * 128], g_plo[4096 * 128];   // pooled split
__device__ __align__(16) bf16 g_w1h[512 * 128],  g_w1l[512 * 128];
__device__ __align__(16) bf16 g_w2h[256 * 512],  g_w2l[256 * 512];
__device__ __align__(16) bf16 g_w3h[128 * 256],  g_w3l[128 * 256];
__device__ __align__(16) bf16 g_a1h[4096 * 512], g_a1l[4096 * 512];
__device__ __align__(16) bf16 g_a2h[4096 * 256], g_a2l[4096 * 256];

// smem layout per buffer (bytes): AHI 0, ALO 10240, BHI 20480, BLO 30720.
// Row stride 80 B (32 bf16 data + 8 pad) -> conflict-free ldmatrix, 16B-mult.
#define BUFSZ      40960
#define SMEM_BYTES 81920

// ================= helpers =================
__device__ __forceinline__ unsigned smem_u32(const void* p) {
    unsigned a;
    asm("{ .reg .u64 t; cvta.to.shared.u64 t, %1; cvt.u32.u64 %0, t; }" : "=r"(a) : "l"(p));
    return a;
}
__device__ __forceinline__ void cp16(unsigned dst, const void* src) {
    asm volatile("cp.async.ca.shared.global [%0], [%1], 16;\n" :: "r"(dst), "l"(src));
}
__device__ __forceinline__ void cp_commit() { asm volatile("cp.async.commit_group;\n"); }

__device__ __forceinline__ void ldsm4(unsigned r[4], unsigned addr) {
    asm volatile("ldmatrix.sync.aligned.m8n8.x4.shared.b16 {%0,%1,%2,%3}, [%4];"
                 : "=r"(r[0]), "=r"(r[1]), "=r"(r[2]), "=r"(r[3]) : "r"(addr));
}
__device__ __forceinline__ void mma16816(float c[4], const unsigned a[4], const unsigned b[2]) {
    asm volatile("mma.sync.aligned.m16n8k16.row.col.f32.bf16.bf16.f32 "
                 "{%0,%1,%2,%3}, {%4,%5,%6,%7}, {%8,%9}, {%0,%1,%2,%3};"
                 : "+f"(c[0]), "+f"(c[1]), "+f"(c[2]), "+f"(c[3])
                 : "r"(a[0]), "r"(a[1]), "r"(a[2]), "r"(a[3]), "r"(b[0]), "r"(b[1]));
}
__device__ __forceinline__ void split2(float v, bf16& h, bf16& l) {
    h = __float2bfloat16(v);
    l = __float2bfloat16(v - __bfloat162float(h));
}

// ================= staging: one 128x32 chunk of A(hi,lo) + B(hi,lo) =================
template<int K>
__device__ __forceinline__ void stage_chunk(unsigned sb, int buf,
        const bf16* Ah, const bf16* Al, const bf16* Bh, const bf16* Bl,
        int m0, int n0, int kc, int tid) {
    unsigned dst0 = sb + (unsigned)buf * BUFSZ;
    int r = tid >> 2, ch = tid & 3;                 // r<128, ch<4 (16B units)
    unsigned doff = (unsigned)(r * 80 + ch * 16);
    long aoff = (long)(m0 + r) * K + kc * 32 + ch * 8;
    long boff = (long)(n0 + r) * K + kc * 32 + ch * 8;
    cp16(dst0 +         doff, Ah + aoff);
    cp16(dst0 + 10240 + doff, Al + aoff);
    cp16(dst0 + 20480 + doff, Bh + boff);
    cp16(dst0 + 30720 + doff, Bl + boff);
    cp_commit();
}

// ================= GEMM mainloop: C[128,128] += split(A) @ split(B)^T =================
template<int K>
__device__ __forceinline__ void gemm_main(unsigned sb,
        const bf16* Ah, const bf16* Al, const bf16* Bh, const bf16* Bl,
        int m0, int n0, float c[2][4][4], int tid) {
    constexpr int KC = K / 32;
    int wid = tid >> 5, lane = tid & 31;
    int wm = wid >> 2, wn = wid & 3;

    stage_chunk<K>(sb, 0, Ah, Al, Bh, Bl, m0, n0, 0, tid);

    for (int kc = 0; kc < KC; ++kc) {
        if (kc + 1 < KC) {
            stage_chunk<K>(sb, (kc + 1) & 1, Ah, Al, Bh, Bl, m0, n0, kc + 1, tid);
            asm volatile("cp.async.wait_group 1;\n");
        } else {
            asm volatile("cp.async.wait_group 0;\n");
        }
        __syncthreads();

        unsigned base = sb + (unsigned)(kc & 1) * BUFSZ;
        #pragma unroll
        for (int ks = 0; ks < 2; ++ks) {
            unsigned a_h[2][4], a_l[2][4];
            #pragma unroll
            for (int mi = 0; mi < 2; ++mi) {
                unsigned arow = (unsigned)(wm * 32 + mi * 16 + (lane & 15));
                unsigned aaddr = base + arow * 80 + ks * 32 + ((lane >> 4) << 4);
                ldsm4(a_h[mi], aaddr);
                ldsm4(a_l[mi], aaddr + 10240);
            }
            unsigned b_h[4][2], b_l[4][2];
            #pragma unroll
            for (int nj = 0; nj < 2; ++nj) {
                unsigned brow = (unsigned)(wn * 32 + nj * 16 + (lane & 7) + ((lane & 16) >> 1));
                unsigned baddr = base + 20480 + brow * 80 + ks * 32 + (((lane >> 3) & 1) << 4);
                unsigned t[4];
                ldsm4(t, baddr);
                b_h[nj * 2][0] = t[0]; b_h[nj * 2][1] = t[1];
                b_h[nj * 2 + 1][0] = t[2]; b_h[nj * 2 + 1][1] = t[3];
                ldsm4(t, baddr + 10240);
                b_l[nj * 2][0] = t[0]; b_l[nj * 2][1] = t[1];
                b_l[nj * 2 + 1][0] = t[2]; b_l[nj * 2 + 1][1] = t[3];
            }
            #pragma unroll
            for (int mi = 0; mi < 2; ++mi)
                #pragma unroll
                for (int ni = 0; ni < 4; ++ni) {
                    mma16816(c[mi][ni], a_h[mi], b_h[ni]);   // hi*hi
                    mma16816(c[mi][ni], a_h[mi], b_l[ni]);   // hi*lo
                    mma16816(c[mi][ni], a_l[mi], b_h[ni]);   // lo*hi
                }
        }
        __syncthreads();
    }
}

// ================= epilogue: bias+relu, split, store to global =================
template<int N>
__device__ __forceinline__ void epi_store(float c[2][4][4], const float* bias,
        bf16* Oh, bf16* Ol, int m0, int n0, int tid) {
    int wid = tid >> 5, lane = tid & 31;
    int wm = wid >> 2, wn = wid & 3;
    int g = lane >> 2, tig = lane & 3;
    #pragma unroll
    for (int mi = 0; mi < 2; ++mi)
        #pragma unroll
        for (int ni = 0; ni < 4; ++ni) {
            int col = n0 + wn * 32 + ni * 8 + 2 * tig;
            float b0v = bias[col], b1v = bias[col + 1];
            #pragma unroll
            for (int h = 0; h < 2; ++h) {
                int row = m0 + wm * 32 + mi * 16 + g + h * 8;
                float v0 = fmaxf(c[mi][ni][h * 2 + 0] + b0v, 0.f);
                float v1 = fmaxf(c[mi][ni][h * 2 + 1] + b1v, 0.f);
                bf162 hh, ll;
                split2(v0, hh.x, ll.x);
                split2(v1, hh.y, ll.y);
                *reinterpret_cast<bf162*>(Oh + (long)row * N + col) = hh;
                *reinterpret_cast<bf162*>(Ol + (long)row * N + col) = ll;
            }
        }
}

// ================= 0) prep: pooling (split out) + weight split =================
__global__ void prep_kernel(const int* __restrict__ x,
                            const int* __restrict__ lengths,
                            const float* __restrict__ emb,
                            const float* __restrict__ W1,
                            const float* __restrict__ W2,
                            const float* __restrict__ W3) {
    if (blockIdx.x < 512) {
        int gwarp = (blockIdx.x * 256 + threadIdx.x) >> 5;
        int lane  = threadIdx.x & 31;
        const int* xr = x + gwarp * T_SEQ;
        int len = lengths[gwarp];
        const float4* emb4 = (const float4*)emb;
        float4 acc = make_float4(0.f, 0.f, 0.f, 0.f);
        int t = 0;
        for (; t + 8 <= len; t += 8) {
            int4 ia = *(const int4*)(xr + t);
            int4 ib = *(const int4*)(xr + t + 4);
            float4 v0 = emb4[ia.x * 32 + lane];
            float4 v1 = emb4[ia.y * 32 + lane];
            float4 v2 = emb4[ia.z * 32 + lane];
            float4 v3 = emb4[ia.w * 32 + lane];
            float4 v4 = emb4[ib.x * 32 + lane];
            float4 v5 = emb4[ib.y * 32 + lane];
            float4 v6 = emb4[ib.z * 32 + lane];
            float4 v7 = emb4[ib.w * 32 + lane];
            acc.x += ((v0.x + v1.x) + (v2.x + v3.x)) + ((v4.x + v5.x) + (v6.x + v7.x));
            acc.y += ((v0.y + v1.y) + (v2.y + v3.y)) + ((v4.y + v5.y) + (v6.y + v7.y));
            acc.z += ((v0.z + v1.z) + (v2.z + v3.z)) + ((v4.z + v5.z) + (v6.z + v7.z));
            acc.w += ((v0.w + v1.w) + (v2.w + v3.w)) + ((v4.w + v5.w) + (v6.w + v7.w));
        }
        for (; t < len; ++t) {
            float4 a = emb4[xr[t] * 32 + lane];
            acc.x += a.x; acc.y += a.y; acc.z += a.z; acc.w += a.w;
        }
        float inv = 1.0f / (float)len;
        float vv[4] = {acc.x * inv, acc.y * inv, acc.z * inv, acc.w * inv};
        bf162 h01, l01, h23, l23;
        split2(vv[0], h01.x, l01.x); split2(vv[1], h01.y, l01.y);
        split2(vv[2], h23.x, l23.x); split2(vv[3], h23.y, l23.y);
        long base = (long)gwarp * 128 + 4 * lane;
        *reinterpret_cast<bf162*>(g_phi + base)     = h01;
        *reinterpret_cast<bf162*>(g_phi + base + 2) = h23;
        *reinterpret_cast<bf162*>(g_plo + base)     = l01;
        *reinterpret_cast<bf162*>(g_plo + base + 2) = l23;
    } else {
        int idx = (blockIdx.x - 512) * 256 + threadIdx.x;
        if (idx < 65536) {
            bf16 h, l; split2(W1[idx], h, l);
            g_w1h[idx] = h; g_w1l[idx] = l;
        } else if (idx < 65536 + 131072) {
            int i2 = idx - 65536;
            bf16 h, l; split2(W2[i2], h, l);
            g_w2h[i2] = h; g_w2l[i2] = l;
        } else if (idx < 65536 + 131072 + 32768) {
            int i3 = idx - 65536 - 131072;
            bf16 h, l; split2(W3[i3], h, l);
            g_w3h[i3] = h; g_w3l[i3] = l;
        }
    }
}

// ================= layer kernels =================
__global__ void __launch_bounds__(512) l1_kernel(const float* __restrict__ b1) {
    extern __shared__ __align__(16) unsigned char smem[];
    unsigned sb = smem_u32(smem);
    int tid = threadIdx.x;
    int m0 = blockIdx.x * 128, n0 = blockIdx.y * 128;
    float c[2][4][4];
    #pragma unroll
    for (int i = 0; i < 2; ++i)
        #pragma unroll
        for (int j = 0; j < 4; ++j)
            #pragma unroll
            for (int q = 0; q < 4; ++q) c[i][j][q] = 0.f;
    gemm_main<128>(sb, g_phi, g_plo, g_w1h, g_w1l, m0, n0, c, tid);
    epi_store<512>(c, b1, g_a1h, g_a1l, m0, n0, tid);
}

__global__ void __launch_bounds__(512) l2_kernel(const float* __restrict__ b2) {
    extern __shared__ __align__(16) unsigned char smem[];
    unsigned sb = smem_u32(smem);
    int tid = threadIdx.x;
    int m0 = blockIdx.x * 128, n0 = blockIdx.y * 128;
    float c[2][4][4];
    #pragma unroll
    for (int i = 0; i < 2; ++i)
        #pragma unroll
        for (int j = 0; j < 4; ++j)
            #pragma unroll
            for (int q = 0; q < 4; ++q) c[i][j][q] = 0.f;
    gemm_main<512>(sb, g_a1h, g_a1l, g_w2h, g_w2l, m0, n0, c, tid);
    epi_store<256>(c, b2, g_a2h, g_a2l, m0, n0, tid);
}

__global__ void __launch_bounds__(512) l3_kernel(const float* __restrict__ b3,
                                                 const float* __restrict__ W4,
                                                 const float* __restrict__ b4,
                                                 float* __restrict__ out) {
    extern __shared__ __align__(16) unsigned char smem[];
    unsigned sb = smem_u32(smem);
    int tid = threadIdx.x;
    int m0 = blockIdx.x * 128;
    float c[2][4][4];
    #pragma unroll
    for (int i = 0; i < 2; ++i)
        #pragma unroll
        for (int j = 0; j < 4; ++j)
            #pragma unroll
            for (int q = 0; q < 4; ++q) c[i][j][q] = 0.f;
    gemm_main<256>(sb, g_a2h, g_a2l, g_w3h, g_w3l, m0, 0, c, tid);

    // h3 (relu'd fp32) -> smem [128][130]
    float* h3 = (float*)smem;
    {
        int wid = tid >> 5, lane = tid & 31;
        int wm = wid >> 2, wn = wid & 3;
        int g = lane >> 2, tig = lane & 3;
        #pragma unroll
        for (int mi = 0; mi < 2; ++mi)
            #pragma unroll
            for (int ni = 0; ni < 4; ++ni) {
                int col = wn * 32 + ni * 8 + 2 * tig;
                float b0v = b3[col], b1v = b3[col + 1];
                #pragma unroll
                for (int h = 0; h < 2; ++h) {
                    int row = wm * 32 + mi * 16 + g + h * 8;
                    h3[row * 130 + col]     = fmaxf(c[mi][ni][h * 2 + 0] + b0v, 0.f);
                    h3[row * 130 + col + 1] = fmaxf(c[mi][ni][h * 2 + 1] + b1v, 0.f);
                }
            }
    }
    __syncthreads();

    // fused layer 4
    if (tid < 256) {
        int r = tid >> 1, jo = tid & 1;
        float acc = b4[jo];
        #pragma unroll 8
        for (int k = 0; k < 128; ++k)
            acc += h3[r * 130 + k] * W4[jo * 128 + k];
        out[(m0 + r) * 2 + jo] = acc;
    }
}

// ================= launch =================
extern "C" void kernel_launch(void* const* d_in, const int* in_sizes, int n_in,
                              void* d_out, int out_size) {
    const int*   x       = (const int*)  d_in[0];
    const int*   lengths = (const int*)  d_in[1];
    const float* emb     = (const float*)d_in[2];
    const float* W1      = (const float*)d_in[3];
    const float* b1      = (const float*)d_in[4];
    const float* W2      = (const float*)d_in[5];
    const float* b2      = (const float*)d_in[6];
    const float* W3      = (const float*)d_in[7];
    const float* b3      = (const float*)d_in[8];
    const float* W4      = (const float*)d_in[9];
    const float* b4      = (const float*)d_in[10];
    float* out = (float*)d_out;

    cudaFuncSetAttribute(l1_kernel, cudaFuncAttributeMaxDynamicSharedMemorySize, SMEM_BYTES);
    cudaFuncSetAttribute(l2_kernel, cudaFuncAttributeMaxDynamicSharedMemorySize, SMEM_BYTES);
    cudaFuncSetAttribute(l3_kernel, cudaFuncAttributeMaxDynamicSharedMemorySize, SMEM_BYTES);

    prep_kernel<<<1408, 256>>>(x, lengths, emb, W1, W2, W3);
    l1_kernel<<<dim3(32, 4), 512, SMEM_BYTES>>>(b1);
    l2_kernel<<<dim3(32, 2), 512, SMEM_BYTES>>>(b2);
    l3_kernel<<<dim3(32, 1), 512, SMEM_BYTES>>>(b3, W4, b4, out);
}

// round 14
// speedup vs baseline: 2.1282x; 1.2682x over previous
#include <cuda_runtime.h>
#include <cuda_bf16.h>

#define N_BATCH 4096
#define T_SEQ   200

typedef __nv_bfloat16  bf16;
typedef __nv_bfloat162 bf162;

// ================= device globals (split bf16) =================
__device__ __align__(16) bf16 g_phi[4096 * 128], g_plo[4096 * 128];   // pooled split
__device__ __align__(16) bf16 g_w1h[512 * 128],  g_w1l[512 * 128];
__device__ __align__(16) bf16 g_w2h[256 * 512],  g_w2l[256 * 512];
__device__ __align__(16) bf16 g_w3h[128 * 256],  g_w3l[128 * 256];
__device__ __align__(16) bf16 g_a1h[4096 * 512], g_a1l[4096 * 512];
__device__ __align__(16) bf16 g_a2h[4096 * 256], g_a2l[4096 * 256];

// smem per buffer (bytes): AHI 0 (64x80), ALO 5120, BHI 10240 (128x80), BLO 20480.
// Row stride 80 B (32 bf16 data + 8 pad) -> conflict-free ldmatrix, 16B-mult.
#define BUFSZ      30720
#define SMEM_BYTES 61440

// ================= helpers =================
__device__ __forceinline__ unsigned smem_u32(const void* p) {
    unsigned a;
    asm("{ .reg .u64 t; cvta.to.shared.u64 t, %1; cvt.u32.u64 %0, t; }" : "=r"(a) : "l"(p));
    return a;
}
__device__ __forceinline__ void cp16(unsigned dst, const void* src) {
    asm volatile("cp.async.ca.shared.global [%0], [%1], 16;\n" :: "r"(dst), "l"(src));
}
__device__ __forceinline__ void cp_commit() { asm volatile("cp.async.commit_group;\n"); }

__device__ __forceinline__ void ldsm4(unsigned r[4], unsigned addr) {
    asm volatile("ldmatrix.sync.aligned.m8n8.x4.shared.b16 {%0,%1,%2,%3}, [%4];"
                 : "=r"(r[0]), "=r"(r[1]), "=r"(r[2]), "=r"(r[3]) : "r"(addr));
}
__device__ __forceinline__ void mma16816(float c[4], const unsigned a[4], const unsigned b[2]) {
    asm volatile("mma.sync.aligned.m16n8k16.row.col.f32.bf16.bf16.f32 "
                 "{%0,%1,%2,%3}, {%4,%5,%6,%7}, {%8,%9}, {%0,%1,%2,%3};"
                 : "+f"(c[0]), "+f"(c[1]), "+f"(c[2]), "+f"(c[3])
                 : "r"(a[0]), "r"(a[1]), "r"(a[2]), "r"(a[3]), "r"(b[0]), "r"(b[1]));
}
__device__ __forceinline__ void split2(float v, bf16& h, bf16& l) {
    h = __float2bfloat16(v);
    l = __float2bfloat16(v - __bfloat162float(h));
}

// ================= staging: one 64x32 A chunk + 128x32 B chunk (hi,lo) =================
template<int K>
__device__ __forceinline__ void stage_chunk(unsigned sb, int buf,
        const bf16* Ah, const bf16* Al, const bf16* Bh, const bf16* Bl,
        int m0, int n0, int kc, int tid) {
    unsigned dst0 = sb + (unsigned)buf * BUFSZ;
    // A: 64 rows
    {
        int r = tid >> 2, ch = tid & 3;             // r<64, ch<4
        unsigned doff = (unsigned)(r * 80 + ch * 16);
        long aoff = (long)(m0 + r) * K + kc * 32 + ch * 8;
        cp16(dst0 +        doff, Ah + aoff);
        cp16(dst0 + 5120 + doff, Al + aoff);
    }
    // B: 128 rows, two passes
    #pragma unroll
    for (int i = 0; i < 2; ++i) {
        int idx = tid + 256 * i;
        int r = idx >> 2, ch = idx & 3;             // r<128, ch<4
        unsigned doff = (unsigned)(r * 80 + ch * 16);
        long boff = (long)(n0 + r) * K + kc * 32 + ch * 8;
        cp16(dst0 + 10240 + doff, Bh + boff);
        cp16(dst0 + 20480 + doff, Bl + boff);
    }
    cp_commit();
}

// ================= GEMM mainloop: C[64,128] += split(A) @ split(B)^T =================
// 256 thr = 8 warps: wm = wid>>2 (2), wn = wid&3 (4); warp tile 32x32.
template<int K>
__device__ __forceinline__ void gemm_main(unsigned sb,
        const bf16* Ah, const bf16* Al, const bf16* Bh, const bf16* Bl,
        int m0, int n0, float c[2][4][4], int tid) {
    constexpr int KC = K / 32;
    int wid = tid >> 5, lane = tid & 31;
    int wm = wid >> 2, wn = wid & 3;

    stage_chunk<K>(sb, 0, Ah, Al, Bh, Bl, m0, n0, 0, tid);

    for (int kc = 0; kc < KC; ++kc) {
        if (kc + 1 < KC) {
            stage_chunk<K>(sb, (kc + 1) & 1, Ah, Al, Bh, Bl, m0, n0, kc + 1, tid);
            asm volatile("cp.async.wait_group 1;\n");
        } else {
            asm volatile("cp.async.wait_group 0;\n");
        }
        __syncthreads();

        unsigned base = sb + (unsigned)(kc & 1) * BUFSZ;
        #pragma unroll
        for (int ks = 0; ks < 2; ++ks) {
            unsigned a_h[2][4], a_l[2][4];
            #pragma unroll
            for (int mi = 0; mi < 2; ++mi) {
                unsigned arow = (unsigned)(wm * 32 + mi * 16 + (lane & 15));
                unsigned aaddr = base + arow * 80 + ks * 32 + ((lane >> 4) << 4);
                ldsm4(a_h[mi], aaddr);
                ldsm4(a_l[mi], aaddr + 5120);
            }
            unsigned b_h[4][2], b_l[4][2];
            #pragma unroll
            for (int nj = 0; nj < 2; ++nj) {
                unsigned brow = (unsigned)(wn * 32 + nj * 16 + (lane & 7) + ((lane & 16) >> 1));
                unsigned baddr = base + 10240 + brow * 80 + ks * 32 + (((lane >> 3) & 1) << 4);
                unsigned t[4];
                ldsm4(t, baddr);
                b_h[nj * 2][0] = t[0]; b_h[nj * 2][1] = t[1];
                b_h[nj * 2 + 1][0] = t[2]; b_h[nj * 2 + 1][1] = t[3];
                ldsm4(t, baddr + 10240);
                b_l[nj * 2][0] = t[0]; b_l[nj * 2][1] = t[1];
                b_l[nj * 2 + 1][0] = t[2]; b_l[nj * 2 + 1][1] = t[3];
            }
            #pragma unroll
            for (int mi = 0; mi < 2; ++mi)
                #pragma unroll
                for (int ni = 0; ni < 4; ++ni) {
                    mma16816(c[mi][ni], a_h[mi], b_h[ni]);   // hi*hi
                    mma16816(c[mi][ni], a_h[mi], b_l[ni]);   // hi*lo
                    mma16816(c[mi][ni], a_l[mi], b_h[ni]);   // lo*hi
                }
        }
        __syncthreads();
    }
}

// ================= epilogue: bias+relu, split, store to global =================
template<int N>
__device__ __forceinline__ void epi_store(float c[2][4][4], const float* bias,
        bf16* Oh, bf16* Ol, int m0, int n0, int tid) {
    int wid = tid >> 5, lane = tid & 31;
    int wm = wid >> 2, wn = wid & 3;
    int g = lane >> 2, tig = lane & 3;
    #pragma unroll
    for (int mi = 0; mi < 2; ++mi)
        #pragma unroll
        for (int ni = 0; ni < 4; ++ni) {
            int col = n0 + wn * 32 + ni * 8 + 2 * tig;
            float b0v = bias[col], b1v = bias[col + 1];
            #pragma unroll
            for (int h = 0; h < 2; ++h) {
                int row = m0 + wm * 32 + mi * 16 + g + h * 8;
                float v0 = fmaxf(c[mi][ni][h * 2 + 0] + b0v, 0.f);
                float v1 = fmaxf(c[mi][ni][h * 2 + 1] + b1v, 0.f);
                bf162 hh, ll;
                split2(v0, hh.x, ll.x);
                split2(v1, hh.y, ll.y);
                *reinterpret_cast<bf162*>(Oh + (long)row * N + col) = hh;
                *reinterpret_cast<bf162*>(Ol + (long)row * N + col) = ll;
            }
        }
}

// ================= 0) prep: pooling (split out) + weight split =================
__global__ void prep_kernel(const int* __restrict__ x,
                            const int* __restrict__ lengths,
                            const float* __restrict__ emb,
                            const float* __restrict__ W1,
                            const float* __restrict__ W2,
                            const float* __restrict__ W3) {
    if (blockIdx.x < 512) {
        int gwarp = (blockIdx.x * 256 + threadIdx.x) >> 5;
        int lane  = threadIdx.x & 31;
        const int* xr = x + gwarp * T_SEQ;
        int len = lengths[gwarp];
        const float4* emb4 = (const float4*)emb;
        float4 acc = make_float4(0.f, 0.f, 0.f, 0.f);
        int t = 0;
        for (; t + 8 <= len; t += 8) {
            int4 ia = *(const int4*)(xr + t);
            int4 ib = *(const int4*)(xr + t + 4);
            float4 v0 = emb4[ia.x * 32 + lane];
            float4 v1 = emb4[ia.y * 32 + lane];
            float4 v2 = emb4[ia.z * 32 + lane];
            float4 v3 = emb4[ia.w * 32 + lane];
            float4 v4 = emb4[ib.x * 32 + lane];
            float4 v5 = emb4[ib.y * 32 + lane];
            float4 v6 = emb4[ib.z * 32 + lane];
            float4 v7 = emb4[ib.w * 32 + lane];
            acc.x += ((v0.x + v1.x) + (v2.x + v3.x)) + ((v4.x + v5.x) + (v6.x + v7.x));
            acc.y += ((v0.y + v1.y) + (v2.y + v3.y)) + ((v4.y + v5.y) + (v6.y + v7.y));
            acc.z += ((v0.z + v1.z) + (v2.z + v3.z)) + ((v4.z + v5.z) + (v6.z + v7.z));
            acc.w += ((v0.w + v1.w) + (v2.w + v3.w)) + ((v4.w + v5.w) + (v6.w + v7.w));
        }
        for (; t < len; ++t) {
            float4 a = emb4[xr[t] * 32 + lane];
            acc.x += a.x; acc.y += a.y; acc.z += a.z; acc.w += a.w;
        }
        float inv = 1.0f / (float)len;
        float vv[4] = {acc.x * inv, acc.y * inv, acc.z * inv, acc.w * inv};
        bf162 h01, l01, h23, l23;
        split2(vv[0], h01.x, l01.x); split2(vv[1], h01.y, l01.y);
        split2(vv[2], h23.x, l23.x); split2(vv[3], h23.y, l23.y);
        long base = (long)gwarp * 128 + 4 * lane;
        *reinterpret_cast<bf162*>(g_phi + base)     = h01;
        *reinterpret_cast<bf162*>(g_phi + base + 2) = h23;
        *reinterpret_cast<bf162*>(g_plo + base)     = l01;
        *reinterpret_cast<bf162*>(g_plo + base + 2) = l23;
    } else {
        int idx = (blockIdx.x - 512) * 256 + threadIdx.x;
        if (idx < 65536) {
            bf16 h, l; split2(W1[idx], h, l);
            g_w1h[idx] = h; g_w1l[idx] = l;
        } else if (idx < 65536 + 131072) {
            int i2 = idx - 65536;
            bf16 h, l; split2(W2[i2], h, l);
            g_w2h[i2] = h; g_w2l[i2] = l;
        } else if (idx < 65536 + 131072 + 32768) {
            int i3 = idx - 65536 - 131072;
            bf16 h, l; split2(W3[i3], h, l);
            g_w3h[i3] = h; g_w3l[i3] = l;
        }
    }
}

// ================= layer kernels =================
__global__ void __launch_bounds__(256) l1_kernel(const float* __restrict__ b1) {
    extern __shared__ __align__(16) unsigned char smem[];
    unsigned sb = smem_u32(smem);
    int tid = threadIdx.x;
    int m0 = blockIdx.x * 64, n0 = blockIdx.y * 128;
    float c[2][4][4];
    #pragma unroll
    for (int i = 0; i < 2; ++i)
        #pragma unroll
        for (int j = 0; j < 4; ++j)
            #pragma unroll
            for (int q = 0; q < 4; ++q) c[i][j][q] = 0.f;
    gemm_main<128>(sb, g_phi, g_plo, g_w1h, g_w1l, m0, n0, c, tid);
    epi_store<512>(c, b1, g_a1h, g_a1l, m0, n0, tid);
}

__global__ void __launch_bounds__(256) l2_kernel(const float* __restrict__ b2) {
    extern __shared__ __align__(16) unsigned char smem[];
    unsigned sb = smem_u32(smem);
    int tid = threadIdx.x;
    int m0 = blockIdx.x * 64, n0 = blockIdx.y * 128;
    float c[2][4][4];
    #pragma unroll
    for (int i = 0; i < 2; ++i)
        #pragma unroll
        for (int j = 0; j < 4; ++j)
            #pragma unroll
            for (int q = 0; q < 4; ++q) c[i][j][q] = 0.f;
    gemm_main<512>(sb, g_a1h, g_a1l, g_w2h, g_w2l, m0, n0, c, tid);
    epi_store<256>(c, b2, g_a2h, g_a2l, m0, n0, tid);
}

__global__ void __launch_bounds__(256) l3_kernel(const float* __restrict__ b3,
                                                 const float* __restrict__ W4,
                                                 const float* __restrict__ b4,
                                                 float* __restrict__ out) {
    extern __shared__ __align__(16) unsigned char smem[];
    unsigned sb = smem_u32(smem);
    int tid = threadIdx.x;
    int m0 = blockIdx.x * 64;
    float c[2][4][4];
    #pragma unroll
    for (int i = 0; i < 2; ++i)
        #pragma unroll
        for (int j = 0; j < 4; ++j)
            #pragma unroll
            for (int q = 0; q < 4; ++q) c[i][j][q] = 0.f;
    gemm_main<256>(sb, g_a2h, g_a2l, g_w3h, g_w3l, m0, 0, c, tid);

    // h3 (relu'd fp32) -> smem [64][130]
    float* h3 = (float*)smem;
    {
        int wid = tid >> 5, lane = tid & 31;
        int wm = wid >> 2, wn = wid & 3;
        int g = lane >> 2, tig = lane & 3;
        #pragma unroll
        for (int mi = 0; mi < 2; ++mi)
            #pragma unroll
            for (int ni = 0; ni < 4; ++ni) {
                int col = wn * 32 + ni * 8 + 2 * tig;
                float b0v = b3[col], b1v = b3[col + 1];
                #pragma unroll
                for (int h = 0; h < 2; ++h) {
                    int row = wm * 32 + mi * 16 + g + h * 8;
                    h3[row * 130 + col]     = fmaxf(c[mi][ni][h * 2 + 0] + b0v, 0.f);
                    h3[row * 130 + col + 1] = fmaxf(c[mi][ni][h * 2 + 1] + b1v, 0.f);
                }
            }
    }
    __syncthreads();

    // fused layer 4 (64 rows x 2 outputs = 128 threads)
    if (tid < 128) {
        int r = tid >> 1, jo = tid & 1;
        float acc = b4[jo];
        #pragma unroll 8
        for (int k = 0; k < 128; ++k)
            acc += h3[r * 130 + k] * W4[jo * 128 + k];
        out[(m0 + r) * 2 + jo] = acc;
    }
}

// ================= launch =================
extern "C" void kernel_launch(void* const* d_in, const int* in_sizes, int n_in,
                              void* d_out, int out_size) {
    const int*   x       = (const int*)  d_in[0];
    const int*   lengths = (const int*)  d_in[1];
    const float* emb     = (const float*)d_in[2];
    const float* W1      = (const float*)d_in[3];
    const float* b1      = (const float*)d_in[4];
    const float* W2      = (const float*)d_in[5];
    const float* b2      = (const float*)d_in[6];
    const float* W3      = (const float*)d_in[7];
    const float* b3      = (const float*)d_in[8];
    const float* W4      = (const float*)d_in[9];
    const float* b4      = (const float*)d_in[10];
    float* out = (float*)d_out;

    cudaFuncSetAttribute(l1_kernel, cudaFuncAttributeMaxDynamicSharedMemorySize, SMEM_BYTES);
    cudaFuncSetAttribute(l2_kernel, cudaFuncAttributeMaxDynamicSharedMemorySize, SMEM_BYTES);
    cudaFuncSetAttribute(l3_kernel, cudaFuncAttributeMaxDynamicSharedMemorySize, SMEM_BYTES);

    prep_kernel<<<1408, 256>>>(x, lengths, emb, W1, W2, W3);
    l1_kernel<<<dim3(64, 4), 256, SMEM_BYTES>>>(b1);
    l2_kernel<<<dim3(64, 2), 256, SMEM_BYTES>>>(b2);
    l3_kernel<<<dim3(64, 1), 256, SMEM_BYTES>>>(b3, W4, b4, out);
}